// round 5
// baseline (speedup 1.0000x reference)
#include <cuda_runtime.h>
#include <math.h>

#define NT     250000
#define NNODE  20000
#define NREL   64
#define RPF    8
#define EMBD   64
#define NCLS   16
#define NRP    (NNODE * RPF)          // 160000

// ---------------- scratch (device globals; no allocation) ----------------
__device__ __align__(16) float d_l1[NT * RPF];        // 8 MB (t-order)
__device__ __align__(16) float d_l2[NT * RPF];        // 8 MB (t-order)
__device__ __align__(16) float d_l1o[NT * RPF];       // 8 MB (csr_o order)
__device__ __align__(16) float d_l2s[NT * RPF];       // 8 MB (csr_s order)
__device__ __align__(16) float d_colsum[NRP];
__device__ __align__(16) float d_rowsum[NRP];
__device__ __align__(16) float d_h [NNODE * EMBD];    // 5 MB
__device__ __align__(16) float d_g [NNODE * RPF * NCLS]; // 10 MB, L2-resident

// CSR scratch
__device__ int d_cnt_s[NNODE], d_off_s[NNODE + 1], d_cur_s[NNODE];
__device__ int d_cnt_o[NNODE], d_off_o[NNODE + 1], d_cur_o[NNODE];
__device__ int2 d_csr_s[NT];   // edges grouped by s; payload (t, o)
__device__ int2 d_csr_o[NT];   // edges grouped by o; payload (t, s)

__device__ __forceinline__ void red_add_v4(float* addr, float a, float b, float c, float d) {
    asm volatile("red.global.v4.f32.add [%0], {%1, %2, %3, %4};"
                 :: "l"(addr), "f"(a), "f"(b), "f"(c), "f"(d) : "memory");
}

// ---------------- K0: init ----------------
__global__ void k_init(float* __restrict__ logits, const float* __restrict__ bias2) {
    int i = blockIdx.x * blockDim.x + threadIdx.x;
    int stride = gridDim.x * blockDim.x;
    for (int j = i; j < NRP; j += stride)          { d_colsum[j] = 0.f; d_rowsum[j] = 0.f; }
    for (int j = i; j < NNODE; j += stride)        { d_cnt_s[j] = 0; d_cnt_o[j] = 0; }
    for (int j = i; j < NNODE * EMBD; j += stride) d_h[j] = 0.f;
    for (int j = i; j < NNODE * NCLS; j += stride) logits[j] = bias2[j & 15];
}

// ---------------- CSR build --------------------------------------------------
__global__ void k_hist(const int* __restrict__ hrow, const int* __restrict__ vcol) {
    int t = blockIdx.x * blockDim.x + threadIdx.x;
    if (t >= NT) return;
    atomicAdd(&d_cnt_s[__ldg(&hrow[t])], 1);
    atomicAdd(&d_cnt_o[__ldg(&vcol[t])], 1);
}

// grid = 2: block 0 scans cnt_s -> off_s/cur_s, block 1 scans cnt_o.
__global__ void __launch_bounds__(1024) k_scan() {
    const int* cnt = (blockIdx.x == 0) ? d_cnt_s : d_cnt_o;
    int* off       = (blockIdx.x == 0) ? d_off_s : d_off_o;
    int* cur       = (blockIdx.x == 0) ? d_cur_s : d_cur_o;
    const int n = NNODE;

    __shared__ int wsum[32];
    __shared__ int s_carry;
    int tid = threadIdx.x, lane = tid & 31, wid = tid >> 5;
    if (tid == 0) s_carry = 0;
    __syncthreads();
    for (int base = 0; base < n; base += 1024) {
        int i = base + tid;
        int v = (i < n) ? cnt[i] : 0;
        int x = v;
#pragma unroll
        for (int d = 1; d < 32; d <<= 1) {
            int y = __shfl_up_sync(0xffffffffu, x, d);
            if (lane >= d) x += y;
        }
        if (lane == 31) wsum[wid] = x;
        __syncthreads();
        if (wid == 0) {
            int w = wsum[lane];
#pragma unroll
            for (int d = 1; d < 32; d <<= 1) {
                int y = __shfl_up_sync(0xffffffffu, w, d);
                if (lane >= d) w += y;
            }
            wsum[lane] = w;
        }
        __syncthreads();
        int incl = x + (wid > 0 ? wsum[wid - 1] : 0);
        int carry = s_carry;
        if (i < n) { int e = carry + incl - v; off[i] = e; cur[i] = e; }
        __syncthreads();
        if (tid == 1023) s_carry = carry + incl;
        __syncthreads();
    }
    if (threadIdx.x == 0) off[n] = s_carry;
}

// ---------------- K1: l1 = rm@W1+b1 ; l2 = softmax(rm@W2+b2) ---------------
// (4th launch -> profiled by ncu)
__global__ void __launch_bounds__(256) k1_edge(
    const float* __restrict__ rm,
    const float* __restrict__ W1, const float* __restrict__ b1v,
    const float* __restrict__ W2, const float* __restrict__ b2v)
{
    int warp = (blockIdx.x * blockDim.x + threadIdx.x) >> 5;
    if (warp >= (NT / 16)) return;
    int lane = threadIdx.x & 31;
    int r  = lane & 7;
    int hc = lane >> 3;

    float w1[16], w2[16];
#pragma unroll
    for (int i = 0; i < 16; i++) {
        w1[i] = __ldg(&W1[(hc * 16 + i) * 8 + r]);
        w2[i] = __ldg(&W2[(hc * 16 + i) * 8 + r]);
    }
    float bb1 = __ldg(&b1v[r]);
    float bb2 = __ldg(&b2v[r]);

    int t0 = warp * 16;
#pragma unroll 2
    for (int e = 0; e < 16; e++) {
        int t = t0 + e;
        const float4* row = reinterpret_cast<const float4*>(rm + (size_t)t * 64 + hc * 16);
        float p1 = 0.f, p2 = 0.f;
#pragma unroll
        for (int q = 0; q < 4; q++) {
            float4 v = __ldg(&row[q]);
            p1 += v.x * w1[4*q] + v.y * w1[4*q+1] + v.z * w1[4*q+2] + v.w * w1[4*q+3];
            p2 += v.x * w2[4*q] + v.y * w2[4*q+1] + v.z * w2[4*q+2] + v.w * w2[4*q+3];
        }
        p1 += __shfl_xor_sync(0xffffffffu, p1, 8);
        p1 += __shfl_xor_sync(0xffffffffu, p1, 16);
        p2 += __shfl_xor_sync(0xffffffffu, p2, 8);
        p2 += __shfl_xor_sync(0xffffffffu, p2, 16);

        float l1v = p1 + bb1;
        float z   = p2 + bb2;
        float m = z;
        m = fmaxf(m, __shfl_xor_sync(0xffffffffu, m, 1));
        m = fmaxf(m, __shfl_xor_sync(0xffffffffu, m, 2));
        m = fmaxf(m, __shfl_xor_sync(0xffffffffu, m, 4));
        float ev = __expf(z - m);
        float se = ev;
        se += __shfl_xor_sync(0xffffffffu, se, 1);
        se += __shfl_xor_sync(0xffffffffu, se, 2);
        se += __shfl_xor_sync(0xffffffffu, se, 4);
        float l2v = ev / se;   // relu(softmax) == softmax

        if (hc == 0) {
            d_l1[t * 8 + r] = l1v;
            d_l2[t * 8 + r] = l2v;
        }
    }
}

__global__ void k_scatter(const int* __restrict__ hrow, const int* __restrict__ vcol) {
    int t = blockIdx.x * blockDim.x + threadIdx.x;
    if (t >= NT) return;
    int s = hrow[t], o = vcol[t];
    int ps = atomicAdd(&d_cur_s[s], 1);
    d_csr_s[ps] = make_int2(t, o);
    int po = atomicAdd(&d_cur_o[o], 1);
    d_csr_o[po] = make_int2(t, s);
}

// ---------------- K2: colsum/rowsum via CSR + reorder l1/l2 ----------------
// 8-lane subgroup per node. Also writes l1 in csr_o order (l1o) and l2 in
// csr_s order (l2s) so k3/k5 stream contiguously.
__global__ void __launch_bounds__(256) k2_sums() {
    __shared__ float sc, sr;
    if (threadIdx.x == 0) { sc = 0.f; sr = 0.f; }
    __syncthreads();

    int sub = (blockIdx.x * blockDim.x + threadIdx.x) >> 3;
    int r = threadIdx.x & 7;
    if (sub < NNODE) {
        int o = sub;
        int beg = d_off_o[o], end = d_off_o[o + 1];
        float S = 0.f;
        for (int j = beg; j < end; j++) {
            int t = d_csr_o[j].x;
            float v = d_l1[t * 8 + r];
            d_l1o[j * 8 + r] = v;
            S += v;
        }
        if (r == 0) atomicAdd(&sc, S);
        else        atomicAdd(&d_colsum[o * r], S);
    } else if (sub < 2 * NNODE) {
        int s = sub - NNODE;
        int beg = d_off_s[s], end = d_off_s[s + 1];
        float S = 0.f;
        for (int j = beg; j < end; j++) {
            int t = d_csr_s[j].x;
            float v = d_l2[t * 8 + r];
            d_l2s[j * 8 + r] = v;
            S += v;
        }
        if (r == 0) atomicAdd(&sr, S);
        else        atomicAdd(&d_rowsum[s * r], S);
    }
    __syncthreads();
    if (threadIdx.x == 0) {
        atomicAdd(&d_colsum[0], sc);
        atomicAdd(&d_rowsum[0], sr);
    }
}

// ---------------- K3: warp per o; W1 rows in regs; red.v4 into h ------------
// 16-lane halves process 2 edges per iteration; l1o reads are streaming.
__global__ void __launch_bounds__(256) k3_layer1(const float* __restrict__ W)
{
    int o = (blockIdx.x * blockDim.x + threadIdx.x) >> 5;
    if (o >= NNODE) return;
    int lane = threadIdx.x & 31;
    int q = lane & 15;
    int half = lane >> 4;

    float invc = 1.f / d_colsum[o * (lane & 7)];

    float4 w[8];
#pragma unroll
    for (int r = 0; r < 8; r++)
        w[r] = __ldg(reinterpret_cast<const float4*>(W + (size_t)(o * r) * 64 + 4 * q));

    int beg = d_off_o[o], end = d_off_o[o + 1];
    for (int j = beg; j < end; j += 2) {
        int jj = j + half;
        bool act = (jj < end);
        int jl = act ? jj : (end - 1);
        int s = d_csr_o[jl].y;
        float av = 0.f;
        if (q < 8) av = d_l1o[jl * 8 + (lane & 7)] * invc;

        float ax = 0.f, ay = 0.f, az = 0.f, aw = 0.f;
#pragma unroll
        for (int r = 0; r < 8; r++) {
            float a = __shfl_sync(0xffffffffu, av, (lane & 16) + r);
            ax += a * w[r].x; ay += a * w[r].y; az += a * w[r].z; aw += a * w[r].w;
        }
        if (act) red_add_v4(d_h + (size_t)s * 64 + 4 * q, ax, ay, az, aw);
    }
}

// ---------------- K4: g[node, rr, c] = relu(h+b1) @ W2cat ------------------
__global__ void __launch_bounds__(256) k4_gemm(
    const float* __restrict__ W2, const float* __restrict__ bias1)
{
    __shared__ float hs[32][129];
    __shared__ __align__(16) float ws[32][128];
    int m0 = blockIdx.x * 128;
    int tid = threadIdx.x;
    int tx = tid & 15;
    int ty = tid >> 4;

    float acc[8][8];
#pragma unroll
    for (int i = 0; i < 8; i++)
#pragma unroll
        for (int j = 0; j < 8; j++) acc[i][j] = 0.f;

    for (int kt = 0; kt < 2; kt++) {
        {
            int kk  = tid & 31;
            int nl0 = tid >> 5;
            float bv = __ldg(&bias1[kt * 32 + kk]);
#pragma unroll
            for (int it = 0; it < 16; it++) {
                int nl = nl0 + it * 8;
                int node = m0 + nl;
                float v = 0.f;
                if (node < NNODE) v = fmaxf(d_h[node * 64 + kt * 32 + kk] + bv, 0.f);
                hs[kk][nl] = v;
            }
        }
        {
            int n  = tid & 127;
            int kb = tid >> 7;
            int rr = n >> 4, c = n & 15;
#pragma unroll
            for (int it = 0; it < 16; it++) {
                int kk2 = kb + it * 2;
                ws[kk2][n] = __ldg(&W2[rr * 1024 + (kt * 32 + kk2) * 16 + c]);
            }
        }
        __syncthreads();
#pragma unroll
        for (int k = 0; k < 32; k++) {
            float av[8];
#pragma unroll
            for (int i = 0; i < 8; i++) av[i] = hs[k][tx + 16 * i];
            float4 b0 = *reinterpret_cast<const float4*>(&ws[k][ty * 8]);
            float4 b1 = *reinterpret_cast<const float4*>(&ws[k][ty * 8 + 4]);
            float bv[8] = {b0.x, b0.y, b0.z, b0.w, b1.x, b1.y, b1.z, b1.w};
#pragma unroll
            for (int i = 0; i < 8; i++)
#pragma unroll
                for (int j = 0; j < 8; j++) acc[i][j] += av[i] * bv[j];
        }
        __syncthreads();
    }
#pragma unroll
    for (int i = 0; i < 8; i++) {
        int node = m0 + tx + 16 * i;
        if (node < NNODE) {
            *reinterpret_cast<float4*>(d_g + node * 128 + ty * 8) =
                make_float4(acc[i][0], acc[i][1], acc[i][2], acc[i][3]);
            *reinterpret_cast<float4*>(d_g + node * 128 + ty * 8 + 4) =
                make_float4(acc[i][4], acc[i][5], acc[i][6], acc[i][7]);
        }
    }
}

// ---------------- K5: warp per s; keys k = s*r, r=0..7 ----------------------
// l2s reads streaming; g row gathered from L2; one atomic per (r,c) per s.
__global__ void __launch_bounds__(256) k5_layer2(float* __restrict__ logits)
{
    __shared__ float sacc[16];
    if (threadIdx.x < 16) sacc[threadIdx.x] = 0.f;
    __syncthreads();

    int s = (blockIdx.x * blockDim.x + threadIdx.x) >> 5;
    int lane = threadIdx.x & 31;
    int half = lane >> 4;
    int c = lane & 15;

    float inv[4]; int rrv[4], nnv[4];
#pragma unroll
    for (int j = 0; j < 4; j++) {
        int r = 2 * j + half;
        int k = s * r;
        inv[j] = 1.f / fmaxf(d_rowsum[k], 1e-6f);
        rrv[j] = k / NNODE;
        nnv[j] = k - rrv[j] * NNODE;
    }

    float acc[4] = {0.f, 0.f, 0.f, 0.f};
    int beg = d_off_s[s], end = d_off_s[s + 1];
    for (int j = beg; j < end; j++) {
        int o = d_csr_s[j].y;
        float l2v = 0.f;
        if (lane < 8) l2v = d_l2s[j * 8 + lane];
        const float* gb = d_g + (size_t)o * 128 + c;
#pragma unroll
        for (int jj = 0; jj < 4; jj++) {
            float a = __shfl_sync(0xffffffffu, l2v, 2 * jj + half);
            acc[jj] += a * __ldg(gb + rrv[jj] * 16);
        }
    }
#pragma unroll
    for (int j = 0; j < 4; j++) {
        int r = 2 * j + half;
        float v = acc[j] * inv[j];
        if (r == 0) atomicAdd(&sacc[c], v);
        else        atomicAdd(&logits[nnv[j] * 16 + c], v);
    }
    __syncthreads();
    if (threadIdx.x < 16) atomicAdd(&logits[threadIdx.x], sacc[threadIdx.x]);
}

// ---------------- launch ----------------------------------------------------
extern "C" void kernel_launch(void* const* d_in, const int* in_sizes, int n_in,
                              void* d_out, int out_size) {
    const float* rm    = (const float*)d_in[0];
    const int*   hrow  = (const int*)  d_in[1];
    const int*   vcol  = (const int*)  d_in[4];
    const float* W_l1  = (const float*)d_in[5];
    const float* b_l1  = (const float*)d_in[6];
    const float* W_l2  = (const float*)d_in[7];
    const float* b_l2  = (const float*)d_in[8];
    const float* wts1  = (const float*)d_in[9];
    const float* wts2  = (const float*)d_in[10];
    const float* bias1 = (const float*)d_in[11];
    const float* bias2 = (const float*)d_in[12];
    float* logits = (float*)d_out;

    k_init<<<1280, 256>>>(logits, bias2);
    k_hist<<<(NT + 255) / 256, 256>>>(hrow, vcol);
    k_scan<<<2, 1024>>>();
    k1_edge<<<(NT / 16 * 32 + 255) / 256, 256>>>(rm, W_l1, b_l1, W_l2, b_l2);  // 4th -> profiled
    k_scatter<<<(NT + 255) / 256, 256>>>(hrow, vcol);
    k2_sums<<<(2 * NNODE * 8 + 255) / 256, 256>>>();
    k3_layer1<<<(NNODE * 32 + 255) / 256, 256>>>(wts1);
    k4_gemm<<<(NNODE + 127) / 128, 256>>>(wts2, bias1);
    k5_layer2<<<(NNODE * 32 + 255) / 256, 256>>>(logits);
}

// round 7
// speedup vs baseline: 1.1919x; 1.1919x over previous
#include <cuda_runtime.h>
#include <math.h>

#define NT     250000
#define NNODE  20000
#define NREL   64
#define RPF    8
#define EMBD   64
#define NCLS   16
#define NRP    (NNODE * RPF)          // 160000
#define NKEY   139994                 // max key = 19999*7; keys in [0, NKEY)

// ---------------- scratch (device globals; no allocation) ----------------
__device__ __align__(16) float d_l1[NT * RPF];        // 8 MB (t-order)
__device__ __align__(16) float d_l2[NT * RPF];        // 8 MB (t-order)
__device__ __align__(16) float d_l1o[NT * RPF];       // 8 MB (csr_o order)
__device__ __align__(16) float d_l2s[NT * RPF];       // 8 MB (csr_s order)
__device__ __align__(16) float d_S[NNODE * RPF];      // partial colsums per (o,r)
__device__ __align__(16) float d_T[NNODE * RPF];      // partial rowsums per (s,r)
__device__ __align__(16) float d_colsum[NRP];
__device__ __align__(16) float d_rowsum[NRP];
__device__ __align__(16) float d_h [NNODE * EMBD];    // 5 MB
__device__ __align__(16) float d_g [NNODE * RPF * NCLS]; // 10 MB, L2-resident

// CSR scratch
__device__ int d_cnt_s[NNODE], d_off_s[NNODE + 1], d_cur_s[NNODE];
__device__ int d_cnt_o[NNODE], d_off_o[NNODE + 1], d_cur_o[NNODE];
__device__ int2 d_csr_s[NT];   // edges grouped by s (sorted by t); payload (t, o)
__device__ int2 d_csr_o[NT];   // edges grouped by o (sorted by t); payload (t, s)

__device__ __forceinline__ void red_add_v4(float* addr, float a, float b, float c, float d) {
    asm volatile("red.global.v4.f32.add [%0], {%1, %2, %3, %4};"
                 :: "l"(addr), "f"(a), "f"(b), "f"(c), "f"(d) : "memory");
}

// ---------------- K0: init ----------------
__global__ void k_init(float* __restrict__ logits, const float* __restrict__ bias2) {
    int i = blockIdx.x * blockDim.x + threadIdx.x;
    int stride = gridDim.x * blockDim.x;
    for (int j = i; j < NRP; j += stride)          { d_colsum[j] = 0.f; d_rowsum[j] = 0.f; }
    for (int j = i; j < NNODE; j += stride)        { d_cnt_s[j] = 0; d_cnt_o[j] = 0; }
    for (int j = i; j < NNODE * EMBD; j += stride) d_h[j] = 0.f;
    for (int j = i; j < NNODE * NCLS; j += stride) logits[j] = bias2[j & 15];
}

// ---------------- CSR build --------------------------------------------------
__global__ void k_hist(const int* __restrict__ hrow, const int* __restrict__ vcol) {
    int t = blockIdx.x * blockDim.x + threadIdx.x;
    if (t >= NT) return;
    atomicAdd(&d_cnt_s[__ldg(&hrow[t])], 1);
    atomicAdd(&d_cnt_o[__ldg(&vcol[t])], 1);
}

// grid = 2: block 0 scans cnt_s -> off_s/cur_s, block 1 scans cnt_o.
__global__ void __launch_bounds__(1024) k_scan() {
    const int* cnt = (blockIdx.x == 0) ? d_cnt_s : d_cnt_o;
    int* off       = (blockIdx.x == 0) ? d_off_s : d_off_o;
    int* cur       = (blockIdx.x == 0) ? d_cur_s : d_cur_o;
    const int n = NNODE;

    __shared__ int wsum[32];
    __shared__ int s_carry;
    int tid = threadIdx.x, lane = tid & 31, wid = tid >> 5;
    if (tid == 0) s_carry = 0;
    __syncthreads();
    for (int base = 0; base < n; base += 1024) {
        int i = base + tid;
        int v = (i < n) ? cnt[i] : 0;
        int x = v;
#pragma unroll
        for (int d = 1; d < 32; d <<= 1) {
            int y = __shfl_up_sync(0xffffffffu, x, d);
            if (lane >= d) x += y;
        }
        if (lane == 31) wsum[wid] = x;
        __syncthreads();
        if (wid == 0) {
            int w = wsum[lane];
#pragma unroll
            for (int d = 1; d < 32; d <<= 1) {
                int y = __shfl_up_sync(0xffffffffu, w, d);
                if (lane >= d) w += y;
            }
            wsum[lane] = w;
        }
        __syncthreads();
        int incl = x + (wid > 0 ? wsum[wid - 1] : 0);
        int carry = s_carry;
        if (i < n) { int e = carry + incl - v; off[i] = e; cur[i] = e; }
        __syncthreads();
        if (tid == 1023) s_carry = carry + incl;
        __syncthreads();
    }
    if (threadIdx.x == 0) off[n] = s_carry;
}

// ---------------- K1: l1 = rm@W1+b1 ; l2 = softmax(rm@W2+b2) ---------------
// Shuffle-free. One thread = one edge; rm staged via smem for coalescing.
// (4th launch -> profiled by ncu)
__global__ void __launch_bounds__(256) k1_edge(
    const float* __restrict__ rm,
    const float* __restrict__ W1, const float* __restrict__ b1v,
    const float* __restrict__ W2, const float* __restrict__ b2v)
{
    __shared__ float sw[8][32][33];
    __shared__ __align__(16) float4 w1s[128];
    __shared__ __align__(16) float4 w2s[128];
    __shared__ float b1sh[8], b2sh[8];

    int tid = threadIdx.x;
    if (tid < 128)      w1s[tid]       = __ldg(reinterpret_cast<const float4*>(W1) + tid);
    else                w2s[tid - 128] = __ldg(reinterpret_cast<const float4*>(W2) + (tid - 128));
    if (tid < 8)        b1sh[tid] = __ldg(&b1v[tid]);
    else if (tid < 16)  b2sh[tid - 8] = __ldg(&b2v[tid - 8]);
    __syncthreads();

    int warp = tid >> 5, lane = tid & 31;
    int t0 = blockIdx.x * 256 + warp * 32;

    float acc1[8], acc2[8];
#pragma unroll
    for (int r = 0; r < 8; r++) { acc1[r] = 0.f; acc2[r] = 0.f; }

    int er = lane >> 3;
    int kc = (lane & 7) * 4;

#pragma unroll
    for (int kt = 0; kt < 2; kt++) {
        __syncwarp();
#pragma unroll
        for (int it = 0; it < 8; it++) {
            int e = it * 4 + er;
            int t = t0 + e;
            float4 v = make_float4(0.f, 0.f, 0.f, 0.f);
            if (t < NT)
                v = __ldg(reinterpret_cast<const float4*>(rm + (size_t)t * 64 + kt * 32 + kc));
            sw[warp][e][kc]     = v.x;
            sw[warp][e][kc + 1] = v.y;
            sw[warp][e][kc + 2] = v.z;
            sw[warp][e][kc + 3] = v.w;
        }
        __syncwarp();
#pragma unroll
        for (int k2 = 0; k2 < 32; k2++) {
            float v = sw[warp][lane][k2];
            int k = kt * 32 + k2;
            float4 a0 = w1s[k * 2], a1 = w1s[k * 2 + 1];
            float4 c0 = w2s[k * 2], c1 = w2s[k * 2 + 1];
            acc1[0] += v * a0.x; acc1[1] += v * a0.y; acc1[2] += v * a0.z; acc1[3] += v * a0.w;
            acc1[4] += v * a1.x; acc1[5] += v * a1.y; acc1[6] += v * a1.z; acc1[7] += v * a1.w;
            acc2[0] += v * c0.x; acc2[1] += v * c0.y; acc2[2] += v * c0.z; acc2[3] += v * c0.w;
            acc2[4] += v * c1.x; acc2[5] += v * c1.y; acc2[6] += v * c1.z; acc2[7] += v * c1.w;
        }
    }

    int t = t0 + lane;
    if (t < NT) {
        float l1o[8];
#pragma unroll
        for (int r = 0; r < 8; r++) l1o[r] = acc1[r] + b1sh[r];

        float z[8];
        float m = -1e30f;
#pragma unroll
        for (int r = 0; r < 8; r++) { z[r] = acc2[r] + b2sh[r]; m = fmaxf(m, z[r]); }
        float se = 0.f;
#pragma unroll
        for (int r = 0; r < 8; r++) { z[r] = __expf(z[r] - m); se += z[r]; }
#pragma unroll
        for (int r = 0; r < 8; r++) z[r] = z[r] / se;   // relu(softmax) == softmax

        float4* p1 = reinterpret_cast<float4*>(d_l1 + (size_t)t * 8);
        float4* p2 = reinterpret_cast<float4*>(d_l2 + (size_t)t * 8);
        p1[0] = make_float4(l1o[0], l1o[1], l1o[2], l1o[3]);
        p1[1] = make_float4(l1o[4], l1o[5], l1o[6], l1o[7]);
        p2[0] = make_float4(z[0], z[1], z[2], z[3]);
        p2[1] = make_float4(z[4], z[5], z[6], z[7]);
    }
}

__global__ void k_scatter(const int* __restrict__ hrow, const int* __restrict__ vcol) {
    int t = blockIdx.x * blockDim.x + threadIdx.x;
    if (t >= NT) return;
    int s = hrow[t], o = vcol[t];
    int ps = atomicAdd(&d_cur_s[s], 1);
    d_csr_s[ps] = make_int2(t, o);
    int po = atomicAdd(&d_cur_o[o], 1);
    d_csr_o[po] = make_int2(t, s);
}

// ---------------- K_sort: sort each CSR group by t (determinism) ------------
// Warp per group; rank sort (t unique within group). Groups > 96 left as-is
// (values unaffected, only summation order; Poisson(12.5) never reaches 96).
__global__ void __launch_bounds__(256) k_sort() {
    __shared__ int2 sm[8][96];
    int g = (blockIdx.x * blockDim.x + threadIdx.x) >> 5;
    if (g >= 2 * NNODE) return;
    int w = threadIdx.x >> 5;
    int lane = threadIdx.x & 31;

    int2* csr; int beg, end;
    if (g < NNODE) { csr = d_csr_s; beg = d_off_s[g]; end = d_off_s[g + 1]; }
    else           { int o = g - NNODE; csr = d_csr_o; beg = d_off_o[o]; end = d_off_o[o + 1]; }
    int n = end - beg;
    if (n <= 1 || n > 96) return;

    for (int i = lane; i < n; i += 32) sm[w][i] = csr[beg + i];
    __syncwarp();
    for (int i = lane; i < n; i += 32) {
        int ti = sm[w][i].x;
        int rank = 0;
        for (int j = 0; j < n; j++) rank += (sm[w][j].x < ti);
        csr[beg + rank] = sm[w][i];
    }
}

// ---------------- K2: per-(node,r) partials (t-ascending) + reorder ---------
__global__ void __launch_bounds__(256) k2_sums() {
    int sub = (blockIdx.x * blockDim.x + threadIdx.x) >> 3;
    int r = threadIdx.x & 7;
    if (sub < NNODE) {
        int o = sub;
        int beg = d_off_o[o], end = d_off_o[o + 1];
        float S = 0.f;
        for (int j = beg; j < end; j++) {
            int t = d_csr_o[j].x;
            float v = d_l1[t * 8 + r];
            d_l1o[j * 8 + r] = v;
            S += v;
        }
        d_S[o * 8 + r] = S;
    } else if (sub < 2 * NNODE) {
        int s = sub - NNODE;
        int beg = d_off_s[s], end = d_off_s[s + 1];
        float S = 0.f;
        for (int j = beg; j < end; j++) {
            int t = d_csr_s[j].x;
            float v = d_l2[t * 8 + r];
            d_l2s[j * 8 + r] = v;
            S += v;
        }
        d_T[s * 8 + r] = S;
    }
}

// ---------------- K_combine: colsum/rowsum[k] from partials, r-ascending ----
__global__ void k_combine() {
    int k = blockIdx.x * blockDim.x + threadIdx.x;
    if (k == 0 || k >= NKEY) return;
    float c = 0.f, rs = 0.f;
#pragma unroll
    for (int r = 1; r < 8; r++) {
        if (k % r == 0) {
            int q = k / r;
            if (q < NNODE) { c += d_S[q * 8 + r]; rs += d_T[q * 8 + r]; }
        }
    }
    d_colsum[k] = c;
    d_rowsum[k] = rs;
}

// ---------------- K_fix0: key 0 (r=0 all nodes, then node 0 r=1..7) ---------
__global__ void __launch_bounds__(256) k_fix0() {
    __shared__ float red[256];
    const float* P = (blockIdx.x == 0) ? d_S : d_T;
    float acc = 0.f;
    for (int o = threadIdx.x; o < NNODE; o += 256) acc += P[o * 8 + 0];
    red[threadIdx.x] = acc;
    __syncthreads();
    for (int st = 128; st > 0; st >>= 1) {
        if (threadIdx.x < st) red[threadIdx.x] += red[threadIdx.x + st];
        __syncthreads();
    }
    if (threadIdx.x == 0) {
        float tot = red[0];
#pragma unroll
        for (int r = 1; r < 8; r++) tot += P[r];
        if (blockIdx.x == 0) d_colsum[0] = tot;
        else                 d_rowsum[0] = tot;
    }
}

// ---------------- K3: warp per o; W1 rows in regs; red.v4 into h ------------
__global__ void __launch_bounds__(256) k3_layer1(const float* __restrict__ W)
{
    int o = (blockIdx.x * blockDim.x + threadIdx.x) >> 5;
    if (o >= NNODE) return;
    int lane = threadIdx.x & 31;
    int q = lane & 15;
    int half = lane >> 4;

    float invc = 1.f / d_colsum[o * (lane & 7)];

    float4 w[8];
#pragma unroll
    for (int r = 0; r < 8; r++)
        w[r] = __ldg(reinterpret_cast<const float4*>(W + (size_t)(o * r) * 64 + 4 * q));

    int beg = d_off_o[o], end = d_off_o[o + 1];
    for (int j = beg; j < end; j += 2) {
        int jj = j + half;
        bool act = (jj < end);
        int jl = act ? jj : (end - 1);
        int s = d_csr_o[jl].y;
        float av = 0.f;
        if (q < 8) av = d_l1o[jl * 8 + (lane & 7)] * invc;

        float ax = 0.f, ay = 0.f, az = 0.f, aw = 0.f;
#pragma unroll
        for (int r = 0; r < 8; r++) {
            float a = __shfl_sync(0xffffffffu, av, (lane & 16) + r);
            ax += a * w[r].x; ay += a * w[r].y; az += a * w[r].z; aw += a * w[r].w;
        }
        if (act) red_add_v4(d_h + (size_t)s * 64 + 4 * q, ax, ay, az, aw);
    }
}

// ---------------- K4: g[node, rr, c] = relu(h+b1) @ W2cat ------------------
__global__ void __launch_bounds__(256) k4_gemm(
    const float* __restrict__ W2, const float* __restrict__ bias1)
{
    __shared__ float hs[32][129];
    __shared__ __align__(16) float ws[32][128];
    int m0 = blockIdx.x * 128;
    int tid = threadIdx.x;
    int tx = tid & 15;
    int ty = tid >> 4;

    float acc[8][8];
#pragma unroll
    for (int i = 0; i < 8; i++)
#pragma unroll
        for (int j = 0; j < 8; j++) acc[i][j] = 0.f;

    for (int kt = 0; kt < 2; kt++) {
        {
            int kk  = tid & 31;
            int nl0 = tid >> 5;
            float bv = __ldg(&bias1[kt * 32 + kk]);
#pragma unroll
            for (int it = 0; it < 16; it++) {
                int nl = nl0 + it * 8;
                int node = m0 + nl;
                float v = 0.f;
                if (node < NNODE) v = fmaxf(d_h[node * 64 + kt * 32 + kk] + bv, 0.f);
                hs[kk][nl] = v;
            }
        }
        {
            int n  = tid & 127;
            int kb = tid >> 7;
            int rr = n >> 4, c = n & 15;
#pragma unroll
            for (int it = 0; it < 16; it++) {
                int kk2 = kb + it * 2;
                ws[kk2][n] = __ldg(&W2[rr * 1024 + (kt * 32 + kk2) * 16 + c]);
            }
        }
        __syncthreads();
#pragma unroll
        for (int k = 0; k < 32; k++) {
            float av[8];
#pragma unroll
            for (int i = 0; i < 8; i++) av[i] = hs[k][tx + 16 * i];
            float4 b0 = *reinterpret_cast<const float4*>(&ws[k][ty * 8]);
            float4 b1 = *reinterpret_cast<const float4*>(&ws[k][ty * 8 + 4]);
            float bv[8] = {b0.x, b0.y, b0.z, b0.w, b1.x, b1.y, b1.z, b1.w};
#pragma unroll
            for (int i = 0; i < 8; i++)
#pragma unroll
                for (int j = 0; j < 8; j++) acc[i][j] += av[i] * bv[j];
        }
        __syncthreads();
    }
#pragma unroll
    for (int i = 0; i < 8; i++) {
        int node = m0 + tx + 16 * i;
        if (node < NNODE) {
            *reinterpret_cast<float4*>(d_g + node * 128 + ty * 8) =
                make_float4(acc[i][0], acc[i][1], acc[i][2], acc[i][3]);
            *reinterpret_cast<float4*>(d_g + node * 128 + ty * 8 + 4) =
                make_float4(acc[i][4], acc[i][5], acc[i][6], acc[i][7]);
        }
    }
}

// ---------------- K5: warp per s; keys k = s*r, r=0..7 ----------------------
__global__ void __launch_bounds__(256) k5_layer2(float* __restrict__ logits)
{
    __shared__ float sacc[16];
    if (threadIdx.x < 16) sacc[threadIdx.x] = 0.f;
    __syncthreads();

    int s = (blockIdx.x * blockDim.x + threadIdx.x) >> 5;
    int lane = threadIdx.x & 31;
    int half = lane >> 4;
    int c = lane & 15;

    float inv[4]; int rrv[4], nnv[4];
#pragma unroll
    for (int j = 0; j < 4; j++) {
        int r = 2 * j + half;
        int k = s * r;
        inv[j] = 1.f / fmaxf(d_rowsum[k], 1e-6f);
        rrv[j] = k / NNODE;
        nnv[j] = k - rrv[j] * NNODE;
    }

    float acc[4] = {0.f, 0.f, 0.f, 0.f};
    int beg = d_off_s[s], end = d_off_s[s + 1];
    for (int j = beg; j < end; j++) {
        int o = d_csr_s[j].y;
        float l2v = 0.f;
        if (lane < 8) l2v = d_l2s[j * 8 + lane];
        const float* gb = d_g + (size_t)o * 128 + c;
#pragma unroll
        for (int jj = 0; jj < 4; jj++) {
            float a = __shfl_sync(0xffffffffu, l2v, 2 * jj + half);
            acc[jj] += a * __ldg(gb + rrv[jj] * 16);
        }
    }
#pragma unroll
    for (int j = 0; j < 4; j++) {
        int r = 2 * j + half;
        float v = acc[j] * inv[j];
        if (r == 0) atomicAdd(&sacc[c], v);
        else        atomicAdd(&logits[nnv[j] * 16 + c], v);
    }
    __syncthreads();
    if (threadIdx.x < 16) atomicAdd(&logits[threadIdx.x], sacc[threadIdx.x]);
}

// ---------------- launch ----------------------------------------------------
extern "C" void kernel_launch(void* const* d_in, const int* in_sizes, int n_in,
                              void* d_out, int out_size) {
    const float* rm    = (const float*)d_in[0];
    const int*   hrow  = (const int*)  d_in[1];
    const int*   vcol  = (const int*)  d_in[4];
    const float* W_l1  = (const float*)d_in[5];
    const float* b_l1  = (const float*)d_in[6];
    const float* W_l2  = (const float*)d_in[7];
    const float* b_l2  = (const float*)d_in[8];
    const float* wts1  = (const float*)d_in[9];
    const float* wts2  = (const float*)d_in[10];
    const float* bias1 = (const float*)d_in[11];
    const float* bias2 = (const float*)d_in[12];
    float* logits = (float*)d_out;

    k_init<<<1280, 256>>>(logits, bias2);
    k_hist<<<(NT + 255) / 256, 256>>>(hrow, vcol);
    k_scan<<<2, 1024>>>();
    k1_edge<<<(NT + 255) / 256, 256>>>(rm, W_l1, b_l1, W_l2, b_l2);  // 4th -> profiled
    k_scatter<<<(NT + 255) / 256, 256>>>(hrow, vcol);
    k_sort<<<(2 * NNODE * 32 + 255) / 256, 256>>>();
    k2_sums<<<(2 * NNODE * 8 + 255) / 256, 256>>>();
    k_combine<<<(NKEY + 255) / 256, 256>>>();
    k_fix0<<<2, 256>>>();
    k3_layer1<<<(NNODE * 32 + 255) / 256, 256>>>(wts1);
    k4_gemm<<<(NNODE + 127) / 128, 256>>>(wts2, bias1);
    k5_layer2<<<(NNODE * 32 + 255) / 256, 256>>>(logits);
}